// round 13
// baseline (speedup 1.0000x reference)
#include <cuda_runtime.h>
#include <cuda_bf16.h>

// WaveletTransform: 3-level low-pass pyramid on x[8,32,512,512] fp32.
// out = x, except per-channel:
//   out[0:256,0:256] = down2x(conv3x3(x[0:512,0:512]))        (level 0)
//   out[0:128,0:128] = down2x(conv3x3(level0 result[0:256]^2)) (level 1)
//   out[0: 64,0: 64] = down2x(conv3x3(level1 result[0:128]^2)) (level 2)
// conv = outer([.25,.5,.25],[.25,.5,.25]), zero-padded 'same', even-index
// downsample (center 2i,2j -> taps 2i-1..2i+1).
//
// R13: SINGLE kernel. CTA (k,bc), k=0..3, owns a 64-row strip of channel bc
// through all three levels. Level-0 rows 64k-3..64k+63 computed from x into
// smem (3 halo rows recomputed locally -> no cross-CTA deps, no races),
// owned rows written to out; x-copy for rows 128k..128k+127 (L2-hot: conv
// just read them); level-1 rows 32k-1..32k+31 from smem l0 -> smem l1 (+
// copy-region writes); level-2 rows 16k..16k+15 from smem l1.
// Eliminates K23's 64MB level-0 gmem re-read and the second launch.
// Out is never re-read anywhere -> ALL out stores are .cs.
// Disjoint write ownership:
//   level-0: rows 64k..64k+63, cols (r>=128 ? 0..255 : 128..255)
//   level-1: rows 32k..32k+31, cols (k>=2 ? 0..127 : 64..127)
//   level-2: rows 16k..16k+15, cols 0..63
//   copy:    rows 128k..128k+127, cols (row<256 ? 256..511 : 0..511)

#define BC_TOTAL (8 * 32)
#define H0 512
#define W0C 512

#define L0S 264                       // floats/row: 256 + 8 pad
#define L0_ROWS 67                    // rows 64k-3 .. 64k+63
#define L1S 132                       // floats/row: 128 + 4 pad
#define L1_ROWS 33                    // rows 32k-1 .. 32k+31
#define SMEM_BYTES ((L0_ROWS * L0S + L1_ROWS * L1S) * 4)   // 88176

__device__ __forceinline__ float hfilt(float a, float b, float c) {
    return 0.25f * a + 0.5f * b + 0.25f * c;
}

__global__ void __launch_bounds__(512, 2) wavelet_strip(
    const float* __restrict__ x, float* __restrict__ out)
{
    extern __shared__ float sm[];
    float* l0 = sm;                         // [L0_ROWS][L0S]
    float* l1 = sm + L0_ROWS * L0S;         // [L1_ROWS][L1S]

    const int tid  = threadIdx.x;
    const int lane = tid & 31;
    const int k    = blockIdx.x;            // strip 0..3
    const int bc   = blockIdx.y;

    const float* xp = x   + (size_t)bc * H0 * W0C;
    float*       op = out + (size_t)bc * H0 * W0C;

    // ---- Phase A1: level-0 rows 64k-3..64k+63 -> smem l0 (+owned out) ----
    {
        const int j4   = tid & 63;          // output fl4 group 0..63 (2 warps/row)
        const int team = tid >> 6;          // 0..7
        #pragma unroll
        for (int t = 0; t < 9; t++) {
            const int rl = team + 8 * t;    // 0..71
            if (rl >= L0_ROWS) break;
            const int r0 = 64 * k - 3 + rl; // -3..255
            float4 res = make_float4(0.f, 0.f, 0.f, 0.f);
            if (r0 >= 0) {                  // warp-uniform
                const int rx0 = 2 * r0 - 1;
                #pragma unroll
                for (int a = 0; a < 3; a++) {
                    const int r = rx0 + a;  // <= 511
                    if (r < 0) continue;    // warp-uniform
                    const float wr = (a == 1) ? 0.5f : 0.25f;
                    const float* row = xp + (size_t)r * W0C;
                    const float4* rv =
                        reinterpret_cast<const float4*>(row) + 2 * j4;
                    float4 p0 = rv[0];
                    float4 p1 = rv[1];
                    float left = __shfl_up_sync(0xFFFFFFFFu, p1.w, 1);
                    if ((j4 & 31) == 0)
                        left = (j4 == 0) ? 0.f : row[8 * j4 - 1];
                    res.x += wr * hfilt(left, p0.x, p0.y);
                    res.y += wr * hfilt(p0.y, p0.z, p0.w);
                    res.z += wr * hfilt(p0.w, p1.x, p1.y);
                    res.w += wr * hfilt(p1.y, p1.z, p1.w);
                }
            }
            *reinterpret_cast<float4*>(&l0[rl * L0S + 4 * j4]) = res;
            // owned level-0 out-write: rows 64k..64k+63; skip 128^2 sub-square
            if (rl >= 3 && (r0 >= 128 || j4 >= 32))
                __stcs(reinterpret_cast<float4*>(
                           op + (size_t)r0 * W0C + 4 * j4), res);
        }
    }

    // ---- Phase A2: identity copy, rows 128k..128k+127 ----
    if (k < 2) {
        // rows < 256: cols 256..511 only (64 fl4/row) -> 8192 fl4
        #pragma unroll 4
        for (int q = 0; q < 16; q++) {
            const int idx = tid + 512 * q;
            const int row = 128 * k + (idx >> 6);
            const int j4c = 64 + (idx & 63);
            float4 v = *(reinterpret_cast<const float4*>(
                             xp + (size_t)row * W0C) + j4c);
            __stcs(reinterpret_cast<float4*>(
                       op + (size_t)row * W0C) + j4c, v);
        }
    } else {
        // rows >= 256: full width (128 fl4/row) -> 16384 fl4
        #pragma unroll 4
        for (int q = 0; q < 32; q++) {
            const int idx = tid + 512 * q;
            const int row = 128 * k + (idx >> 7);
            const int j4c = idx & 127;
            float4 v = *(reinterpret_cast<const float4*>(
                             xp + (size_t)row * W0C) + j4c);
            __stcs(reinterpret_cast<float4*>(
                       op + (size_t)row * W0C) + j4c, v);
        }
    }
    __syncthreads();

    // ---- Phase B: level-1 rows 32k-1..32k+31 from l0 -> l1 (+copy out) ----
    {
        const int w = tid >> 5;             // 0..15
        #pragma unroll
        for (int t = 0; t < 3; t++) {
            const int rl = w + 16 * t;      // 0..47
            if (rl >= L1_ROWS) break;
            const int r1 = 32 * k - 1 + rl; // -1..127
            float4 res = make_float4(0.f, 0.f, 0.f, 0.f);
            if (r1 >= 0) {                  // warp-uniform
                const int base = 2 * rl;    // l0 rows base..base+2 (zeros pad)
                #pragma unroll
                for (int a = 0; a < 3; a++) {
                    const float wr = (a == 1) ? 0.5f : 0.25f;
                    const float* row = &l0[(base + a) * L0S];
                    float4 p0 = *reinterpret_cast<const float4*>(row + 8 * lane);
                    float4 p1 = *reinterpret_cast<const float4*>(row + 8 * lane + 4);
                    float left = __shfl_up_sync(0xFFFFFFFFu, p1.w, 1);
                    if (lane == 0) left = 0.f;
                    res.x += wr * hfilt(left, p0.x, p0.y);
                    res.y += wr * hfilt(p0.y, p0.z, p0.w);
                    res.z += wr * hfilt(p0.w, p1.x, p1.y);
                    res.w += wr * hfilt(p1.y, p1.z, p1.w);
                }
            }
            *reinterpret_cast<float4*>(&l1[rl * L1S + 4 * lane]) = res;
            // owned level-1 copy-region write (outside inner 64^2)
            if (rl >= 1 && (k >= 2 || lane >= 16))
                __stcs(reinterpret_cast<float4*>(
                           op + (size_t)r1 * W0C + 4 * lane), res);
        }
    }
    __syncthreads();

    // ---- Phase C: level-2 rows 16k..16k+15 from l1 -> out ----
    if (tid < 256) {
        const int il = tid >> 4;            // 0..15
        const int g  = tid & 15;            // fl4 col group 0..15
        float4 res = make_float4(0.f, 0.f, 0.f, 0.f);
        #pragma unroll
        for (int a = 0; a < 3; a++) {
            const float wr = (a == 1) ? 0.5f : 0.25f;
            const float* row = &l1[(2 * il + a) * L1S];   // zero rows pad
            float4 p0 = *reinterpret_cast<const float4*>(row + 8 * g);
            float4 p1 = *reinterpret_cast<const float4*>(row + 8 * g + 4);
            float left = __shfl_up_sync(0xFFFFFFFFu, p1.w, 1);
            if (g == 0) left = 0.f;         // lanes 0 and 16 both g==0
            res.x += wr * hfilt(left, p0.x, p0.y);
            res.y += wr * hfilt(p0.y, p0.z, p0.w);
            res.z += wr * hfilt(p0.w, p1.x, p1.y);
            res.w += wr * hfilt(p1.y, p1.z, p1.w);
        }
        __stcs(reinterpret_cast<float4*>(
                   op + (size_t)(16 * k + il) * W0C + 4 * g), res);
    }
}

extern "C" void kernel_launch(void* const* d_in, const int* in_sizes, int n_in,
                              void* d_out, int out_size)
{
    (void)in_sizes; (void)n_in; (void)out_size;
    const float* x = (const float*)d_in[0];
    float* out = (float*)d_out;

    static bool attr_set = false;
    if (!attr_set) {
        cudaFuncSetAttribute(wavelet_strip,
                             cudaFuncAttributeMaxDynamicSharedMemorySize,
                             SMEM_BYTES);
        attr_set = true;
    }

    wavelet_strip<<<dim3(4, BC_TOTAL), dim3(512), SMEM_BYTES>>>(x, out);
}

// round 14
// speedup vs baseline: 1.1024x; 1.1024x over previous
#include <cuda_runtime.h>
#include <cuda_bf16.h>

// WaveletTransform: 3-level low-pass pyramid on x[8,32,512,512] fp32.
// out = x, except per-channel:
//   out[0:256,0:256] = down2x(conv3x3(x[0:512,0:512]))        (level 0)
//   out[0:128,0:128] = down2x(conv3x3(level0 result[0:256]^2)) (level 1)
//   out[0: 64,0: 64] = down2x(conv3x3(level1 result[0:128]^2)) (level 2)
// conv = outer([.25,.5,.25],[.25,.5,.25]), zero-padded 'same', even-index
// downsample (center 2i,2j -> taps 2i-1..2i+1).
//
// R14: hazard removed at the DATA level (no cluster barrier):
//  - K1 writes the level-0 sub-square rows<128 & cols<128 to scratch g_l0
//    (16MB device global) instead of out — out there is overwritten by K23
//    anyway, so total store bytes are unchanged.
//  - K23 strips (4 per channel, 256 thr, 17KB smem, all CTAs one wave) read
//    level-0 from scratch for (row<128, cols<128) and from out elsewhere;
//    read set no longer intersects write set -> race-free without sync.
//  - K23 writes (level-1 copy region + level-2) are .cs (never re-read).

#define BC_TOTAL (8 * 32)
#define H0 512
#define W0C 512

#define L1S 132                          // 128 + 4 floats pad
#define L1_ROWS 33

__device__ float g_l0[BC_TOTAL * 128 * 128];   // level-0 sub-square scratch

__device__ __forceinline__ float hfilt(float a, float b, float c) {
    return 0.25f * a + 0.5f * b + 0.25f * c;
}

// ---------------------------------------------------------------------------
// K1: fused identity copy + level-0 conv-down.
// grid (1,64,256), block 256.  (R3 shape; conv store target split)
// ---------------------------------------------------------------------------
__global__ void __launch_bounds__(256) k1_copy_down0(
    const float* __restrict__ x, float* __restrict__ out)
{
    const int j4   = threadIdx.x & 127;          // 0..127 (col/4)
    const int sub  = threadIdx.x >> 7;           // 0..1
    const int base = blockIdx.y * 8 + sub * 4;   // first of 4 rows
    const int bc   = blockIdx.z;

    const float* xp = x   + (size_t)bc * H0 * W0C;
    float*       op = out + (size_t)bc * H0 * W0C;
    float*       sp = g_l0 + (size_t)bc * 128 * 128;

    if (base < 256 && j4 < 64) {
        #pragma unroll
        for (int it = 0; it < 4; it++) {
            const int i  = base + it;
            const int r0 = 2 * i - 1;
            float acc0 = 0.f, acc1 = 0.f, acc2 = 0.f, acc3 = 0.f;
            #pragma unroll
            for (int a = 0; a < 3; a++) {
                const int r = r0 + a;            // <= 511
                if (r < 0) continue;             // warp-uniform
                const float wr = (a == 1) ? 0.5f : 0.25f;
                const float* row = xp + (size_t)r * W0C;
                const float4* rv = reinterpret_cast<const float4*>(row) + 2 * j4;
                float4 p0 = rv[0];
                float4 p1 = rv[1];
                float left = __shfl_up_sync(0xFFFFFFFFu, p1.w, 1);
                if ((j4 & 31) == 0)
                    left = (j4 == 0) ? 0.f : row[8 * j4 - 1];
                acc0 += wr * hfilt(left, p0.x, p0.y);
                acc1 += wr * hfilt(p0.y, p0.z, p0.w);
                acc2 += wr * hfilt(p0.w, p1.x, p1.y);
                acc3 += wr * hfilt(p1.y, p1.z, p1.w);
            }
            float4 res = make_float4(acc0, acc1, acc2, acc3);
            if (i < 128 && j4 < 32)
                *reinterpret_cast<float4*>(sp + (size_t)i * 128 + 4 * j4) = res;
            else
                *reinterpret_cast<float4*>(op + (size_t)i * W0C + 4 * j4) = res;
        }
    } else {
        float4 v[4];
        #pragma unroll
        for (int it = 0; it < 4; it++)
            v[it] = *(reinterpret_cast<const float4*>(
                          xp + (size_t)(base + it) * W0C) + j4);
        #pragma unroll
        for (int it = 0; it < 4; it++)
            __stcs(reinterpret_cast<float4*>(
                       op + (size_t)(base + it) * W0C) + j4, v[it]);
    }
}

// ---------------------------------------------------------------------------
// K23s: strip fused levels 1+2. grid (4, 256), block 256, NO cluster.
// CTA (k, bc): smem holds level-1 rows 32k-1 .. 32k+31 (33 rows; r1<0 = 0).
// Level-0 source: rows<128 & lanes<16 (cols<128) -> g_l0; else out.
// ---------------------------------------------------------------------------
__global__ void __launch_bounds__(256) k23_strip(float* __restrict__ out)
{
    __shared__ float l1[L1_ROWS * L1S];

    const int tid  = threadIdx.x;
    const int lane = tid & 31;
    const int wid  = tid >> 5;                  // 0..7
    const int k    = blockIdx.x;                // strip 0..3
    const int bc   = blockIdx.y;

    float*       op = out  + (size_t)bc * H0 * W0C;
    const float* sp = g_l0 + (size_t)bc * 128 * 128;

    // ---- Phase 1: level-1 conv -> smem rows 0..32 (r1 = 32k-1+r_local) ----
    #pragma unroll
    for (int t = 0; t < 5; t++) {
        const int r_local = 8 * t + wid;        // 0..39; valid <= 32
        if (r_local <= 32) {
            const int r1 = 32 * k - 1 + r_local;   // -1..127
            float acc0 = 0.f, acc1 = 0.f, acc2 = 0.f, acc3 = 0.f;
            if (r1 >= 0) {                      // warp-uniform
                const int r0v = 2 * r1 - 1;
                #pragma unroll
                for (int a = 0; a < 3; a++) {
                    const int r = r0v + a;      // <= 255
                    if (r < 0) continue;        // warp-uniform
                    const float wr = (a == 1) ? 0.5f : 0.25f;
                    // cols 8*lane..8*lane+7: lanes 0..15 = cols 0..127
                    const float* rowp = (r < 128 && lane < 16)
                        ? (sp + (size_t)r * 128)
                        : (op + (size_t)r * W0C);
                    const float4* rv =
                        reinterpret_cast<const float4*>(rowp) + 2 * lane;
                    float4 p0 = rv[0];
                    float4 p1 = rv[1];
                    float left = __shfl_up_sync(0xFFFFFFFFu, p1.w, 1);
                    if (lane == 0) left = 0.f;
                    acc0 += wr * hfilt(left, p0.x, p0.y);
                    acc1 += wr * hfilt(p0.y, p0.z, p0.w);
                    acc2 += wr * hfilt(p0.w, p1.x, p1.y);
                    acc3 += wr * hfilt(p1.y, p1.z, p1.w);
                }
            }
            *reinterpret_cast<float4*>(&l1[r_local * L1S + 4 * lane]) =
                make_float4(acc0, acc1, acc2, acc3);   // zeros when r1 < 0
        }
    }
    __syncthreads();

    // ---- Phase 2a: level-2 rows 16k..16k+15, one float4 per thread ----
    {
        const int i2l = tid >> 4;               // 0..15
        const int g   = tid & 15;               // float4 col group
        float acc0 = 0.f, acc1 = 0.f, acc2 = 0.f, acc3 = 0.f;
        #pragma unroll
        for (int a = 0; a < 3; a++) {
            const int loc = 2 * i2l + a;        // 0..31 (local row -1 = zeros)
            const float* row = &l1[loc * L1S];
            float4 p0 = *reinterpret_cast<const float4*>(row + 8 * g);
            float4 p1 = *reinterpret_cast<const float4*>(row + 8 * g + 4);
            const float wr = (a == 1) ? 0.5f : 0.25f;
            float left = __shfl_up_sync(0xFFFFFFFFu, p1.w, 1);
            if (g == 0) left = 0.f;
            acc0 += wr * hfilt(left, p0.x, p0.y);
            acc1 += wr * hfilt(p0.y, p0.z, p0.w);
            acc2 += wr * hfilt(p0.w, p1.x, p1.y);
            acc3 += wr * hfilt(p1.y, p1.z, p1.w);
        }
        __stcs(reinterpret_cast<float4*>(
                   op + (size_t)(16 * k + i2l) * W0C + 4 * g),
               make_float4(acc0, acc1, acc2, acc3));
    }

    // ---- Phase 2b: copy level-1 rows 32k..32k+31 outside inner 64^2 ----
    #pragma unroll
    for (int q = 0; q < 4; q++) {
        const int idx = tid + 256 * q;          // 0..1023
        const int row = idx >> 5;               // 0..31
        const int j4  = idx & 31;               // 0..31
        const int i   = 32 * k + row;           // 0..127
        if (i >= 64 || j4 >= 16) {
            float4 v = *reinterpret_cast<const float4*>(
                           &l1[(row + 1) * L1S + 4 * j4]);
            __stcs(reinterpret_cast<float4*>(
                       op + (size_t)i * W0C + 4 * j4), v);
        }
    }
}

extern "C" void kernel_launch(void* const* d_in, const int* in_sizes, int n_in,
                              void* d_out, int out_size)
{
    (void)in_sizes; (void)n_in; (void)out_size;
    const float* x = (const float*)d_in[0];
    float* out = (float*)d_out;

    k1_copy_down0<<<dim3(1, 64, BC_TOTAL), dim3(256)>>>(x, out);
    k23_strip    <<<dim3(4, BC_TOTAL), dim3(256)>>>(out);
}

// round 15
// speedup vs baseline: 1.1305x; 1.0254x over previous
#include <cuda_runtime.h>
#include <cuda_bf16.h>
#include <cstdint>

// WaveletTransform: 3-level low-pass pyramid on x[8,32,512,512] fp32.
// out = x, except per-channel:
//   out[0:256,0:256] = down2x(conv3x3(x[0:512,0:512]))        (level 0)
//   out[0:128,0:128] = down2x(conv3x3(level0 result[0:256]^2)) (level 1)
//   out[0: 64,0: 64] = down2x(conv3x3(level1 result[0:128]^2)) (level 2)
// conv = outer([.25,.5,.25],[.25,.5,.25]), zero-padded 'same', even-index
// downsample (center 2i,2j -> taps 2i-1..2i+1).
//
// R15: R12 structure (K1 + 4-strip clustered K23), but the cluster barrier
// between K23's read phase and write phase is now a DSMEM mbarrier
// (4 arrivals, one per strip CTA) instead of barrier.cluster:
//  - no CCTL.IVALL L1D flush, no ~490cyc UCGABAR_WAIT
//  - WAR-only hazard -> relaxed wait is sufficient (loads secured by each
//    CTA's __syncthreads before its arrives)
//  - phase-2a (level-2 conv, smem-only) computed into registers BETWEEN
//    arrive and wait to hide wait latency; stores after the wait.
// K1 unchanged (R3 shape, 78.6us local optimum).

#define BC_TOTAL (8 * 32)
#define H0 512
#define W0C 512

#define L1S 132                          // 128 + 4 floats pad
#define L1_ROWS 33

__device__ __forceinline__ float hfilt(float a, float b, float c) {
    return 0.25f * a + 0.5f * b + 0.25f * c;
}

__device__ __forceinline__ uint32_t smem_u32(const void* p) {
    uint32_t a;
    asm("{ .reg .u64 t; cvta.to.shared.u64 t, %1; cvt.u32.u64 %0, t; }"
        : "=r"(a) : "l"(p));
    return a;
}

// ---------------------------------------------------------------------------
// K1: fused identity copy + level-0 conv-down into top-left 256^2.
// grid (1,64,256), block 256.  (exact R3/R4/R12 version)
// ---------------------------------------------------------------------------
__global__ void __launch_bounds__(256) k1_copy_down0(
    const float* __restrict__ x, float* __restrict__ out)
{
    const int j4   = threadIdx.x & 127;          // 0..127 (col/4)
    const int sub  = threadIdx.x >> 7;           // 0..1
    const int base = blockIdx.y * 8 + sub * 4;   // first of 4 rows
    const int bc   = blockIdx.z;

    const float* xp = x   + (size_t)bc * H0 * W0C;
    float*       op = out + (size_t)bc * H0 * W0C;

    if (base < 256 && j4 < 64) {
        #pragma unroll
        for (int it = 0; it < 4; it++) {
            const int i  = base + it;
            const int r0 = 2 * i - 1;
            float acc0 = 0.f, acc1 = 0.f, acc2 = 0.f, acc3 = 0.f;
            #pragma unroll
            for (int a = 0; a < 3; a++) {
                const int r = r0 + a;            // <= 511
                if (r < 0) continue;             // warp-uniform
                const float wr = (a == 1) ? 0.5f : 0.25f;
                const float* row = xp + (size_t)r * W0C;
                const float4* rv = reinterpret_cast<const float4*>(row) + 2 * j4;
                float4 p0 = rv[0];
                float4 p1 = rv[1];
                float left = __shfl_up_sync(0xFFFFFFFFu, p1.w, 1);
                if ((j4 & 31) == 0)
                    left = (j4 == 0) ? 0.f : row[8 * j4 - 1];
                acc0 += wr * hfilt(left, p0.x, p0.y);
                acc1 += wr * hfilt(p0.y, p0.z, p0.w);
                acc2 += wr * hfilt(p0.w, p1.x, p1.y);
                acc3 += wr * hfilt(p1.y, p1.z, p1.w);
            }
            *reinterpret_cast<float4*>(op + (size_t)i * W0C + 4 * j4) =
                make_float4(acc0, acc1, acc2, acc3);
        }
    } else {
        float4 v[4];
        #pragma unroll
        for (int it = 0; it < 4; it++)
            v[it] = *(reinterpret_cast<const float4*>(
                          xp + (size_t)(base + it) * W0C) + j4);
        #pragma unroll
        for (int it = 0; it < 4; it++)
            __stcs(reinterpret_cast<float4*>(
                       op + (size_t)(base + it) * W0C) + j4, v[it]);
    }
}

// ---------------------------------------------------------------------------
// K23s: strip fused levels 1+2, clustered per channel with mbarrier sync.
// grid (4, 256), block 256, cluster (4,1,1): blockIdx.x = strip k,
// blockIdx.y = channel. smem: level-1 rows 32k-1..32k+31 (r1<0 = zeros).
// ---------------------------------------------------------------------------
__global__ void __launch_bounds__(256) __cluster_dims__(4, 1, 1)
k23_strip(float* __restrict__ out)
{
    __shared__ float l1[L1_ROWS * L1S];
    __shared__ __align__(8) unsigned long long mbar;

    const int tid  = threadIdx.x;
    const int lane = tid & 31;
    const int wid  = tid >> 5;                  // 0..7
    const int k    = blockIdx.x;                // strip 0..3
    const int bc   = blockIdx.y;

    const uint32_t mb = smem_u32(&mbar);

    // init local mbarrier (4 arrivals: one per strip CTA of this channel)
    if (tid == 0) {
        asm volatile("mbarrier.init.shared.b64 [%0], 4;" :: "r"(mb) : "memory");
    }
    __syncthreads();
    // make all CTAs' mbarrier inits visible cluster-wide before any arrive
    asm volatile("barrier.cluster.arrive.aligned;" ::: "memory");
    asm volatile("barrier.cluster.wait.aligned;"   ::: "memory");

    float* op = out + (size_t)bc * H0 * W0C;

    // ---- Phase 1: level-1 conv -> smem rows 0..32 (r1 = 32k-1+r_local) ----
    #pragma unroll
    for (int t = 0; t < 5; t++) {
        const int r_local = 8 * t + wid;        // 0..39; valid <= 32
        if (r_local <= 32) {
            const int r1 = 32 * k - 1 + r_local;   // -1..127
            float acc0 = 0.f, acc1 = 0.f, acc2 = 0.f, acc3 = 0.f;
            if (r1 >= 0) {                      // warp-uniform
                const int r0v = 2 * r1 - 1;
                #pragma unroll
                for (int a = 0; a < 3; a++) {
                    const int r = r0v + a;      // <= 255
                    if (r < 0) continue;        // warp-uniform
                    const float wr = (a == 1) ? 0.5f : 0.25f;
                    const float* row = op + (size_t)r * W0C;
                    const float4* rv =
                        reinterpret_cast<const float4*>(row) + 2 * lane;
                    float4 p0 = rv[0];
                    float4 p1 = rv[1];
                    float left = __shfl_up_sync(0xFFFFFFFFu, p1.w, 1);
                    if (lane == 0) left = 0.f;
                    acc0 += wr * hfilt(left, p0.x, p0.y);
                    acc1 += wr * hfilt(p0.y, p0.z, p0.w);
                    acc2 += wr * hfilt(p0.w, p1.x, p1.y);
                    acc3 += wr * hfilt(p1.y, p1.z, p1.w);
                }
            }
            *reinterpret_cast<float4*>(&l1[r_local * L1S + 4 * lane]) =
                make_float4(acc0, acc1, acc2, acc3);   // zeros when r1 < 0
        }
    }
    __syncthreads();   // all phase-1 loads consumed + smem tile complete

    // ---- signal: this CTA is done READING out[0:256]^2 ----
    if (tid == 0) {
        #pragma unroll
        for (int rk = 0; rk < 4; rk++) {
            asm volatile(
                "{\n\t"
                ".reg .b32 remAddr;\n\t"
                "mapa.shared::cluster.u32 remAddr, %0, %1;\n\t"
                "mbarrier.arrive.relaxed.cluster.shared::cluster.b64 _, [remAddr];\n\t"
                "}"
                :: "r"(mb), "r"(rk) : "memory");
        }
    }

    // ---- Phase 2a compute (smem-only) while the barrier drains ----
    const int i2l = tid >> 4;                   // 0..15
    const int g   = tid & 15;                   // float4 col group
    float4 r2a = make_float4(0.f, 0.f, 0.f, 0.f);
    #pragma unroll
    for (int a = 0; a < 3; a++) {
        const int loc = 2 * i2l + a;            // 0..31 (local row -1 = zeros)
        const float* row = &l1[loc * L1S];
        float4 p0 = *reinterpret_cast<const float4*>(row + 8 * g);
        float4 p1 = *reinterpret_cast<const float4*>(row + 8 * g + 4);
        const float wr = (a == 1) ? 0.5f : 0.25f;
        float left = __shfl_up_sync(0xFFFFFFFFu, p1.w, 1);
        if (g == 0) left = 0.f;
        r2a.x += wr * hfilt(left, p0.x, p0.y);
        r2a.y += wr * hfilt(p0.y, p0.z, p0.w);
        r2a.z += wr * hfilt(p0.w, p1.x, p1.y);
        r2a.w += wr * hfilt(p1.y, p1.z, p1.w);
    }

    // ---- wait: all 4 strips of this channel done reading (WAR => relaxed) ----
    {
        uint32_t done;
        asm volatile(
            "{\n\t"
            ".reg .pred p;\n\t"
            "mbarrier.try_wait.parity.relaxed.cta.shared::cta.b64 p, [%1], 0;\n\t"
            "selp.b32 %0, 1, 0, p;\n\t"
            "}" : "=r"(done) : "r"(mb) : "memory");
        if (!done) {
            asm volatile(
                "{\n\t"
                ".reg .pred P1;\n\t"
                "WL_%=:\n\t"
                "mbarrier.try_wait.parity.relaxed.cta.shared::cta.b64 P1, [%0], 0, 0x989680;\n\t"
                "@P1 bra.uni WD_%=;\n\t"
                "bra.uni WL_%=;\n\t"
                "WD_%=:\n\t"
                "}" :: "r"(mb) : "memory");
        }
    }

    // ---- Phase 2a store: level-2 rows 16k..16k+15 ----
    __stcs(reinterpret_cast<float4*>(
               op + (size_t)(16 * k + i2l) * W0C + 4 * g), r2a);

    // ---- Phase 2b: copy level-1 rows 32k..32k+31 outside inner 64^2 ----
    #pragma unroll
    for (int q = 0; q < 4; q++) {
        const int idx = tid + 256 * q;          // 0..1023
        const int row = idx >> 5;               // 0..31
        const int j4  = idx & 31;               // 0..31
        const int i   = 32 * k + row;           // 0..127
        if (i >= 64 || j4 >= 16) {
            float4 v = *reinterpret_cast<const float4*>(
                           &l1[(row + 1) * L1S + 4 * j4]);
            __stcs(reinterpret_cast<float4*>(
                       op + (size_t)i * W0C + 4 * j4), v);
        }
    }
}

extern "C" void kernel_launch(void* const* d_in, const int* in_sizes, int n_in,
                              void* d_out, int out_size)
{
    (void)in_sizes; (void)n_in; (void)out_size;
    const float* x = (const float*)d_in[0];
    float* out = (float*)d_out;

    k1_copy_down0<<<dim3(1, 64, BC_TOTAL), dim3(256)>>>(x, out);
    k23_strip    <<<dim3(4, BC_TOTAL), dim3(256)>>>(out);
}